// round 16
// baseline (speedup 1.0000x reference)
#include <cuda_runtime.h>
#include <cuda_fp16.h>
#include <cfloat>
#include <cstdint>

#define BB 2048
#define TT 32
#define VV 1024
#define DD 256
#define WINF 6.0f
#define QS   (6.0f / 127.0f)
#define QSI  (127.0f / 6.0f)
#define M2S2 (-2.0f * QS * QS)

// ---------------- static device scratch -------------------------------------
__device__ float g_c2[TT * VV];                                  // 128 KB
__device__ float g_rmin[TT * BB];                                // 256 KB
// A int8 fragments: [t][mtile16(128)][kstep32(8)][lane(32)] uint4
__device__ uint4 g_xa[(size_t)TT * 128 * 8 * 32];                // 16.8 MB
// B int8 fragments: [t][ntile8(128)][kstep32(8)][lanepair(16)] uint4 (2 lanes)
__device__ uint4 g_cb[(size_t)TT * 128 * 8 * 16];                // 8.4 MB
// screened centered scores, fp16: [t][b][v]
__device__ __half g_sc[(size_t)TT * BB * VV];                    // 128 MB

// ---------------- helpers ----------------------------------------------------
__device__ __forceinline__ void mma_s8(int* c, uint32_t a0, uint32_t a1,
                                       uint32_t a2, uint32_t a3,
                                       uint32_t b0, uint32_t b1) {
    asm volatile(
        "mma.sync.aligned.m16n8k32.row.col.s32.s8.s8.s32 "
        "{%0,%1,%2,%3}, {%4,%5,%6,%7}, {%8,%9}, {%0,%1,%2,%3};"
        : "+r"(c[0]), "+r"(c[1]), "+r"(c[2]), "+r"(c[3])
        : "r"(a0), "r"(a1), "r"(a2), "r"(a3), "r"(b0), "r"(b1));
}
__device__ __forceinline__ uint32_t smem_u32(const void* p) {
    uint32_t a;
    asm("{ .reg .u64 t; cvta.to.shared.u64 t, %1; cvt.u32.u64 %0, t; }" : "=r"(a) : "l"(p));
    return a;
}
__device__ __forceinline__ void cp16(uint32_t dst, const void* src) {
    asm volatile("cp.async.cg.shared.global [%0], [%1], 16;" :: "r"(dst), "l"(src));
}
#define CP_COMMIT() asm volatile("cp.async.commit_group;")
#define CP_WAIT(n)  asm volatile("cp.async.wait_group %0;" :: "n"(n))

__device__ __forceinline__ int q8(float v) {
    int q = __float2int_rn(v * QSI);
    return max(-127, min(127, q));
}
__device__ __forceinline__ uint32_t pack4(const float* sm, int stride_is_1_k0,
                                          float a, float b, float c, float d) {
    return (uint32_t)(q8(a) & 255) | ((uint32_t)(q8(b) & 255) << 8) |
           ((uint32_t)(q8(c) & 255) << 16) | ((uint32_t)(q8(d) & 255) << 24);
}

// ---------------- prepass: int8 fragment split of X and C + c2 ---------------
// Grid (192, 32): blocks [0,128) X mtiles; [128,192) C vtiles(16 rows).
__global__ __launch_bounds__(128) void conv_kernel(const float* __restrict__ x,
                                                   const float* __restrict__ cb) {
    __shared__ float sm[16][258];
    __shared__ float psum[16][8];
    const int t = blockIdx.y, tid = threadIdx.x;
    const int lane = tid & 31, grp = lane >> 2, tig = lane & 3;
    if (blockIdx.x < 128) {
        const int mt = blockIdx.x;
#pragma unroll
        for (int j = 0; j < 8; j++) {
            int f = tid + j * 128;
            int r = f >> 6, d4 = f & 63;
            float4 v = *reinterpret_cast<const float4*>(
                x + ((size_t)(mt * 16 + r) * TT + t) * DD + d4 * 4);
            sm[r][d4 * 4 + 0] = v.x; sm[r][d4 * 4 + 1] = v.y;
            sm[r][d4 * 4 + 2] = v.z; sm[r][d4 * 4 + 3] = v.w;
        }
        __syncthreads();
        const int kp = tid >> 5;            // 0..3 -> ksteps kp, kp+4
        uint4* obase = g_xa + ((size_t)(t * 128 + mt) * 8) * 32;
#pragma unroll
        for (int h = 0; h < 2; h++) {
            int ks = kp + h * 4;
            int k0 = ks * 32 + tig * 4;
            uint4 fr;
            fr.x = pack4(0, 0, sm[grp][k0],     sm[grp][k0 + 1],     sm[grp][k0 + 2],     sm[grp][k0 + 3]);
            fr.y = pack4(0, 0, sm[grp + 8][k0], sm[grp + 8][k0 + 1], sm[grp + 8][k0 + 2], sm[grp + 8][k0 + 3]);
            fr.z = pack4(0, 0, sm[grp][k0 + 16],     sm[grp][k0 + 17],     sm[grp][k0 + 18],     sm[grp][k0 + 19]);
            fr.w = pack4(0, 0, sm[grp + 8][k0 + 16], sm[grp + 8][k0 + 17], sm[grp + 8][k0 + 18], sm[grp + 8][k0 + 19]);
            obase[ks * 32 + lane] = fr;
        }
    } else {
        const int vt = blockIdx.x - 128;
#pragma unroll
        for (int j = 0; j < 8; j++) {
            int f = tid + j * 128;
            int r = f >> 6, d4 = f & 63;
            float4 v = *reinterpret_cast<const float4*>(
                cb + ((size_t)t * VV + vt * 16 + r) * DD + d4 * 4);
            sm[r][d4 * 4 + 0] = v.x; sm[r][d4 * 4 + 1] = v.y;
            sm[r][d4 * 4 + 2] = v.z; sm[r][d4 * 4 + 3] = v.w;
        }
        __syncthreads();
        {
            int r = tid >> 3, seg = tid & 7;
            float s = 0.f;
#pragma unroll
            for (int k = 0; k < 32; k++) {
                float v = sm[r][seg * 32 + k];
                s = fmaf(v, v, s);
            }
            psum[r][seg] = s;
        }
        // B fragments: thread covers (nt8 = tid>>6, kq = (tid>>5)&1), ks = kq+{0,2,4,6}
        const int nt8 = tid >> 6, kq = (tid >> 5) & 1;
        const int row = nt8 * 8 + grp;
        uint2* ob2 = reinterpret_cast<uint2*>(
            g_cb + ((size_t)(t * 128 + vt * 2 + nt8) * 8) * 16);
#pragma unroll
        for (int h = 0; h < 4; h++) {
            int ks = kq + h * 2;
            int k0 = ks * 32 + tig * 4;
            uint2 fr;
            fr.x = pack4(0, 0, sm[row][k0],      sm[row][k0 + 1],  sm[row][k0 + 2],  sm[row][k0 + 3]);
            fr.y = pack4(0, 0, sm[row][k0 + 16], sm[row][k0 + 17], sm[row][k0 + 18], sm[row][k0 + 19]);
            ob2[ks * 32 + lane] = fr;
        }
        __syncthreads();
        if (tid < 16) {
            float acc = 0.f;
#pragma unroll
            for (int j = 0; j < 8; j++) acc += psum[tid][j];
            g_c2[t * VV + vt * 16 + tid] = acc;
        }
    }
}

// ---------------- phase 1: int8 GEMM -> fp16 scores + register row-min -------
// Grid (16, 32), 256 threads = 8 warps (2m x 4n). Warp 64x32, block 128x128.
// Slab = 1 kstep32 (A 4KB + B 4KB), 4-buffer ring, CP_WAIT(2).
#define SLAB_B 8192
#define NSLAB 64                              // 8 nch x 8 ksteps
#define DYN_SMEM (4 * SLAB_B + 4096 + 8192)

__global__ __launch_bounds__(256, 2)
void vsq_score_kernel(float* __restrict__ dummy) {
    extern __shared__ char dyn[];
    char*  sbuf = dyn;                                      // 4 x 8KB
    float* c2c  = reinterpret_cast<float*>(dyn + 4 * SLAB_B);
    float* Sv   = reinterpret_cast<float*>(dyn);            // [128][16] (alias)

    const int tid = threadIdx.x;
    const int btile = blockIdx.x, t = blockIdx.y;
    const int wid = tid >> 5, lane = tid & 31;
    const int grp = lane >> 2, tig = lane & 3;
    const int wm = wid >> 2, wn = wid & 3;

    for (int i = tid; i < VV; i += 256) c2c[i] = g_c2[t * VV + i] - 256.0f;
    __syncthreads();

    const uint4* Abase = g_xa + ((size_t)(t * 128 + btile * 8) * 8) * 32;
    const uint4* Bbase = g_cb + ((size_t)(t * 128)) * 8 * 16;

    const uint32_t sb0 = smem_u32(sbuf);
    const int amt = tid >> 5;                 // 0..7 mtile
    const int bnt = tid >> 4, bpr = tid & 15; // nt8 0..15, pair
    auto stage = [&](int s, int buf) {
        const int nch = s >> 3, ks = s & 7;
        uint32_t d = sb0 + (uint32_t)buf * SLAB_B;
        cp16(d + amt * 512 + lane * 16,
             Abase + ((size_t)amt * 8 + ks) * 32 + lane);
        cp16(d + 4096 + bnt * 256 + bpr * 16,
             Bbase + ((size_t)(nch * 16 + bnt) * 8 + ks) * 16 + bpr);
        CP_COMMIT();
    };

    stage(0, 0);
    stage(1, 1);
    stage(2, 2);

    int acc[4][4][4];
#pragma unroll
    for (int a = 0; a < 4; a++)
#pragma unroll
        for (int b = 0; b < 4; b++)
#pragma unroll
            for (int c = 0; c < 4; c++) acc[a][b][c] = 0;

    float bmin[8];
#pragma unroll
    for (int i = 0; i < 8; i++) bmin[i] = FLT_MAX;

    const size_t srowbase = (size_t)t * BB + (size_t)btile * 128;

    for (int s = 0; s < NSLAB; s++) {
        if (s < NSLAB - 3)      { CP_WAIT(2); }
        else if (s == NSLAB - 3) { CP_WAIT(1); }
        else                     { CP_WAIT(0); }
        __syncthreads();
        if (s + 3 < NSLAB) stage(s + 3, (s + 3) & 3);

        char* Asm = sbuf + (s & 3) * SLAB_B;
        char* Bsm = Asm + 4096;
        uint4 af[4];
        uint2 bf[4];
#pragma unroll
        for (int mt = 0; mt < 4; mt++)
            af[mt] = *reinterpret_cast<uint4*>(Asm + (wm * 4 + mt) * 512 + lane * 16);
#pragma unroll
        for (int q = 0; q < 4; q++)
            bf[q] = *reinterpret_cast<uint2*>(Bsm + (wn * 4 + q) * 256 + lane * 8);
#pragma unroll
        for (int q = 0; q < 4; q++)
#pragma unroll
            for (int mt = 0; mt < 4; mt++)
                mma_s8(acc[mt][q], af[mt].x, af[mt].y, af[mt].z, af[mt].w,
                       bf[q].x, bf[q].y);

        if ((s & 7) == 7) {
            const int nch = s >> 3;
#pragma unroll
            for (int q = 0; q < 4; q++) {
                int v = nch * 128 + wn * 32 + q * 8 + tig * 2;
                float c0 = c2c[v], c1 = c2c[v + 1];
#pragma unroll
                for (int mt = 0; mt < 4; mt++) {
                    int r0 = wm * 64 + mt * 16 + grp;
                    float s0 = fmaf(M2S2, (float)acc[mt][q][0], c0);
                    float s1 = fmaf(M2S2, (float)acc[mt][q][1], c1);
                    float s2 = fmaf(M2S2, (float)acc[mt][q][2], c0);
                    float s3 = fmaf(M2S2, (float)acc[mt][q][3], c1);
                    bmin[mt * 2]     = fminf(bmin[mt * 2], fminf(s0, s1));
                    bmin[mt * 2 + 1] = fminf(bmin[mt * 2 + 1], fminf(s2, s3));
                    *reinterpret_cast<__half2*>(&g_sc[(srowbase + r0) * VV + v]) =
                        __floats2half2_rn(s0, s1);
                    *reinterpret_cast<__half2*>(&g_sc[(srowbase + r0 + 8) * VV + v]) =
                        __floats2half2_rn(s2, s3);
                    acc[mt][q][0] = 0; acc[mt][q][1] = 0;
                    acc[mt][q][2] = 0; acc[mt][q][3] = 0;
                }
            }
        }
    }

    // row-min reduce -> g_rmin
    __syncthreads();
#pragma unroll
    for (int mt = 0; mt < 4; mt++) {
#pragma unroll
        for (int h = 0; h < 2; h++) {
            int r = wm * 64 + mt * 16 + grp + h * 8;
            Sv[r * 16 + wn * 4 + tig] = bmin[mt * 2 + h];
        }
    }
    __syncthreads();
    if (tid < 128) {
        float bv = Sv[tid * 16];
#pragma unroll
        for (int u = 1; u < 16; u++) bv = fminf(bv, Sv[tid * 16 + u]);
        g_rmin[srowbase + tid] = bv;
    }
}

// ---------------- phase 2: window scan + exact refine + gather ---------------
__global__ __launch_bounds__(256)
void argmin_kernel(const float* __restrict__ x, const float* __restrict__ cb,
                   float* __restrict__ out) {
    __shared__ int s_list[8][40];
    __shared__ int s_cnt[8];
    const int tid = threadIdx.x, w = tid >> 5, lane = tid & 31;
    const int t = blockIdx.y;

    for (int r = 0; r < 4; r++) {
        const int b = blockIdx.x * 32 + w * 4 + r;
        const __half* srow = g_sc + ((size_t)t * BB + b) * VV;
        const uint4* srow4 = reinterpret_cast<const uint4*>(srow);
        const float win = g_rmin[(size_t)t * BB + b] + WINF;

        if (lane == 0) s_cnt[w] = 0;
        __syncwarp();

#pragma unroll
        for (int i = 0; i < 4; i++) {
            uint4 qv = srow4[i * 32 + lane];
            const uint32_t* u = reinterpret_cast<const uint32_t*>(&qv);
#pragma unroll
            for (int wd = 0; wd < 4; wd++) {
                __half2 h2 = *reinterpret_cast<const __half2*>(&u[wd]);
                float f0 = __low2float(h2), f1 = __high2float(h2);
                int v0 = i * 256 + lane * 8 + wd * 2;
                if (f0 <= win) {
                    int pos = atomicAdd(&s_cnt[w], 1);
                    if (pos < 40) s_list[w][pos] = v0;
                }
                if (f1 <= win) {
                    int pos = atomicAdd(&s_cnt[w], 1);
                    if (pos < 40) s_list[w][pos] = v0 + 1;
                }
            }
        }
        __syncwarp();
        int cnt = s_cnt[w];

        int widx;
        if (cnt == 1) {
            widx = s_list[w][0];
        } else {
            const float* xr = x + ((size_t)b * TT + t) * DD;
            float4 x0 = reinterpret_cast<const float4*>(xr)[lane * 2];
            float4 x1 = reinterpret_cast<const float4*>(xr)[lane * 2 + 1];
            float bestf = FLT_MAX;
            int   bwi = 0x7fffffff;
            if (cnt <= 40) {
                for (int c = 0; c < cnt; c++) {
                    int v = s_list[w][c];
                    const float* cr = cb + ((size_t)t * VV + v) * DD;
                    float4 c0 = reinterpret_cast<const float4*>(cr)[lane * 2];
                    float4 c1 = reinterpret_cast<const float4*>(cr)[lane * 2 + 1];
                    float p = 0.f;
                    p = fmaf(x0.x, c0.x, p); p = fmaf(x0.y, c0.y, p);
                    p = fmaf(x0.z, c0.z, p); p = fmaf(x0.w, c0.w, p);
                    p = fmaf(x1.x, c1.x, p); p = fmaf(x1.y, c1.y, p);
                    p = fmaf(x1.z, c1.z, p); p = fmaf(x1.w, c1.w, p);
#pragma unroll
                    for (int off = 16; off > 0; off >>= 1)
                        p += __shfl_xor_sync(0xffffffffu, p, off);
                    float sc = fmaf(-2.f, p, g_c2[t * VV + v]);
                    if (sc < bestf || (sc == bestf && v < bwi)) { bestf = sc; bwi = v; }
                }
            } else {
                for (int v = 0; v < VV; v++) {
                    const float* cr = cb + ((size_t)t * VV + v) * DD;
                    float4 c0 = reinterpret_cast<const float4*>(cr)[lane * 2];
                    float4 c1 = reinterpret_cast<const float4*>(cr)[lane * 2 + 1];
                    float p = 0.f;
                    p = fmaf(x0.x, c0.x, p); p = fmaf(x0.y, c0.y, p);
                    p = fmaf(x0.z, c0.z, p); p = fmaf(x0.w, c0.w, p);
                    p = fmaf(x1.x, c1.x, p); p = fmaf(x1.y, c1.y, p);
                    p = fmaf(x1.z, c1.z, p); p = fmaf(x1.w, c1.w, p);
#pragma unroll
                    for (int off = 16; off > 0; off >>= 1)
                        p += __shfl_xor_sync(0xffffffffu, p, off);
                    float sc = fmaf(-2.f, p, g_c2[t * VV + v]);
                    if (sc < bestf) { bestf = sc; bwi = v; }
                }
            }
            widx = bwi;
        }

        if (lane == 0)
            out[(size_t)BB * TT * DD + (size_t)b * TT + t] = (float)widx;
        const float4* src = reinterpret_cast<const float4*>(
            cb + ((size_t)t * VV + widx) * DD);
        float4* dst = reinterpret_cast<float4*>(out + ((size_t)b * TT + t) * DD);
        dst[lane]      = src[lane];
        dst[lane + 32] = src[lane + 32];
    }
}

// ---------------------------------------------------------------------------
extern "C" void kernel_launch(void* const* d_in, const int* in_sizes, int n_in,
                              void* d_out, int out_size) {
    const float* x  = (const float*)d_in[0];   // (B, T, D) f32
    const float* cb = (const float*)d_in[1];   // (T, V, D) f32
    float* out = (float*)d_out;

    cudaFuncSetAttribute(vsq_score_kernel, cudaFuncAttributeMaxDynamicSharedMemorySize, DYN_SMEM);
    conv_kernel<<<dim3(192, TT), 128>>>(x, cb);
    vsq_score_kernel<<<dim3(BB / 128, TT), 256, DYN_SMEM>>>(out);
    argmin_kernel<<<dim3(64, TT), 256>>>(x, cb, out);
}